// round 15
// baseline (speedup 1.0000x reference)
#include <cuda_runtime.h>
#include <cuda_fp16.h>

// Problem constants
#define Bb    256
#define Tt    512
#define DIN   128
#define Hh    256
#define DOUT  64
#define KTOT  384
#define LEAK  0.01f

// 64MB fp16 scratch: U[b][t][h] = inputs[b][t] @ W_u^T  (k < DIN part)
__device__ __half g_U[(size_t)Bb * Tt * Hh];

// ---- packed fp32x2 helpers (for gemm2) ----
__device__ __forceinline__ void ffma2(unsigned long long& acc,
                                      unsigned long long a, unsigned long long b) {
    asm("fma.rn.f32x2 %0, %1, %2, %0;" : "+l"(acc) : "l"(a), "l"(b));
}
__device__ __forceinline__ float2 unpackf2(unsigned long long v) {
    float2 r;
    asm("mov.b64 {%0, %1}, %2;" : "=f"(r.x), "=f"(r.y) : "l"(v));
    return r;
}
__device__ __forceinline__ float lrelu(float x) {
    return x > 0.f ? x : LEAK * x;
}

// ============================================================================
// Precompute U = inputs @ W_u^T via fp16 mma (R12 v2 kernel, validated).
// GRID FLIP: (4, 1024) with n-slice on the FAST dim -> the 4 CTAs sharing an
// m-block are launch-adjacent -> inputs re-reads hit L2 (DRAM 320->~130 MB).
// ============================================================================
#define PCPAD 136

__global__ void __launch_bounds__(128)
u_precompute_kernel(const float* __restrict__ inputs,   // [B*T, DIN]
                    const float* __restrict__ W_ih)     // [H, KTOT]
{
    __shared__ __half sA[64 * PCPAD];
    __shared__ __half sW[64 * PCPAD];
    const int t  = threadIdx.x;
    const int n0 = (int)blockIdx.x * 64;    // n-slice: FAST grid dim

    // stage W once (first DIN cols of W_ih rows n0..n0+63)
    for (int i = t; i < 64 * 32; i += 128) {
        int row = i >> 5, c4 = i & 31;
        float4 v = *(const float4*)(W_ih + (size_t)(n0 + row) * KTOT + 4 * c4);
        __half2 h01 = __floats2half2_rn(v.x, v.y);
        __half2 h23 = __floats2half2_rn(v.z, v.w);
        *(uint2*)(sW + row * PCPAD + 4 * c4) =
            make_uint2(*(unsigned*)&h01, *(unsigned*)&h23);
    }

    const int wi = t >> 5, lane = t & 31;
    const int gg = lane >> 2, tg = lane & 3;
    const int mw = wi * 16;

    #pragma unroll 1
    for (int mt = 0; mt < 2; mt++) {
        const int m0 = (int)blockIdx.y * 128 + mt * 64;
        if (mt) __syncthreads();     // prior mma reads of sA done
        for (int i = t; i < 64 * 32; i += 128) {
            int row = i >> 5, c4 = i & 31;
            float4 v = *(const float4*)(inputs + (size_t)(m0 + row) * DIN + 4 * c4);
            __half2 h01 = __floats2half2_rn(v.x, v.y);
            __half2 h23 = __floats2half2_rn(v.z, v.w);
            *(uint2*)(sA + row * PCPAD + 4 * c4) =
                make_uint2(*(unsigned*)&h01, *(unsigned*)&h23);
        }
        __syncthreads();

        float d[8][4];
        #pragma unroll
        for (int nf = 0; nf < 8; nf++)
            #pragma unroll
            for (int c = 0; c < 4; c++) d[nf][c] = 0.f;

        #pragma unroll
        for (int ki = 0; ki < 8; ki++) {
            int k0 = 16 * ki;
            unsigned a0 = *(const unsigned*)(sA + (mw + gg)     * PCPAD + k0 + 2*tg);
            unsigned a1 = *(const unsigned*)(sA + (mw + 8 + gg) * PCPAD + k0 + 2*tg);
            unsigned a2 = *(const unsigned*)(sA + (mw + gg)     * PCPAD + k0 + 2*tg + 8);
            unsigned a3 = *(const unsigned*)(sA + (mw + 8 + gg) * PCPAD + k0 + 2*tg + 8);
            #pragma unroll
            for (int nf = 0; nf < 8; nf++) {
                unsigned b0 = *(const unsigned*)(sW + (8*nf + gg) * PCPAD + k0 + 2*tg);
                unsigned b1 = *(const unsigned*)(sW + (8*nf + gg) * PCPAD + k0 + 2*tg + 8);
                asm("mma.sync.aligned.m16n8k16.row.col.f32.f16.f16.f32 "
                    "{%0,%1,%2,%3}, {%4,%5,%6,%7}, {%8,%9}, {%0,%1,%2,%3};"
                    : "+f"(d[nf][0]), "+f"(d[nf][1]), "+f"(d[nf][2]), "+f"(d[nf][3])
                    : "r"(a0), "r"(a1), "r"(a2), "r"(a3), "r"(b0), "r"(b1));
            }
        }

        #pragma unroll
        for (int nf = 0; nf < 8; nf++) {
            __half2 lo = __floats2half2_rn(d[nf][0], d[nf][1]);
            __half2 hi = __floats2half2_rn(d[nf][2], d[nf][3]);
            size_t r0 = (size_t)(m0 + mw + gg)     * Hh + n0 + 8*nf + 2*tg;
            size_t r1 = (size_t)(m0 + mw + 8 + gg) * Hh + n0 + 8*nf + 2*tg;
            *(unsigned*)&g_U[r0] = *(unsigned*)&lo;
            *(unsigned*)&g_U[r1] = *(unsigned*)&hi;
        }
    }
}

// ============================================================================
// Persistent recurrence on TENSOR CORES: 128 CTAs x 256 threads.
// NEW: A rows 0-7 = h_row0, rows 8-15 = h_row1 (replicated, no zero rows).
// Every lane group gets both rows' results (c0/c1 row0, c2/c3 row1), so the
// epilogue splits 4 ways: gg0/gg1 -> smem install, gg2/gg3 -> gmem stores.
// Row arithmetic is bit-identical to R12. 1 barrier/step.
// ============================================================================
#define SH_PAD 264

__global__ void __launch_bounds__(256, 1)
rnn_persist_kernel(const float* __restrict__ h0,       // [B, H]
                   const float* __restrict__ W_ih,     // [H, KTOT]
                   const float* __restrict__ b_ih,     // [H]
                   float* __restrict__ out_h)          // [B, T+1, H]
{
    __shared__ __half shH[2][2][SH_PAD];   // [buf][row][col]

    const int t    = threadIdx.x;
    const int wi   = t >> 5;               // warp: n-cols [wi*32, wi*32+32)
    const int lane = t & 31;
    const int gg   = lane >> 2;
    const int tg   = lane & 3;
    const int rsel = gg & 1;               // my duty row (epi lanes)
    const bool epi = (gg < 4);             // epilogue duty lanes
    const int mode = (gg >> 1) & 1;        // 0: smem install, 1: gmem store
    const int row0 = (int)blockIdx.x * 2;

    // ---- 1) W_hh as register-resident B fragments (unchanged) ----
    unsigned bfr[4][16][2];
    #pragma unroll
    for (int nt = 0; nt < 4; nt++) {
        const int n = wi * 32 + nt * 8 + gg;
        const float* wr = W_ih + (size_t)n * KTOT + DIN;
        #pragma unroll
        for (int kt = 0; kt < 16; kt++) {
            float2 f0 = __ldg((const float2*)(wr + kt * 16 + 2 * tg));
            float2 f1 = __ldg((const float2*)(wr + kt * 16 + 2 * tg + 8));
            __half2 h0v = __floats2half2_rn(f0.x, f0.y);
            __half2 h1v = __floats2half2_rn(f1.x, f1.y);
            bfr[nt][kt][0] = *(unsigned*)&h0v;
            bfr[nt][kt][1] = *(unsigned*)&h1v;
        }
    }

    // ---- 2) init state buffer 0 = fp16(h0); t=0 fp32 outputs ----
    for (int i = t; i < 2 * Hh; i += 256) {
        int rr = i >> 8, c = i & 255;
        float v = h0[(size_t)(row0 + rr) * Hh + c];
        shH[0][rr][c] = __float2half_rn(v);
        out_h[(size_t)(row0 + rr) * (Tt + 1) * Hh + c] = v;
    }

    // ---- 3) per-lane epilogue constants ----
    int coff[4];
    float2 bi[4];
    #pragma unroll
    for (int nt = 0; nt < 4; nt++) {
        coff[nt] = wi * 32 + nt * 8 + 2 * tg;
        bi[nt] = epi ? __ldg((const float2*)(b_ih + coff[nt]))
                     : make_float2(0.f, 0.f);
    }
    const __half* Ub = g_U + (size_t)(row0 + rsel) * Tt * Hh;
    float* hx = out_h + (size_t)(row0 + rsel) * (Tt + 1) * Hh;

    unsigned cU[4] = {0, 0, 0, 0};
    if (epi) {
        #pragma unroll
        for (int nt = 0; nt < 4; nt++)
            cU[nt] = *(const unsigned*)(Ub + coff[nt]);
    }

    __syncthreads();

    #pragma unroll 1
    for (int step = 0; step < Tt; step++) {
        const int p  = step & 1;
        const int pn = (step + 1 < Tt) ? step + 1 : step;   // clamped prefetch

        unsigned nU[4] = {0, 0, 0, 0};
        if (epi) {
            #pragma unroll
            for (int nt = 0; nt < 4; nt++)
                nU[nt] = *(const unsigned*)(Ub + (size_t)pn * Hh + coff[nt]);
        }

        float d[4][4];
        #pragma unroll
        for (int nt = 0; nt < 4; nt++)
            #pragma unroll
            for (int c = 0; c < 4; c++) d[nt][c] = 0.f;

        // ---- mma: A rows 0-7 = row0, 8-15 = row1 (broadcast LDS) ----
        #pragma unroll
        for (int kt = 0; kt < 16; kt++) {
            unsigned a0 = *(const unsigned*)&shH[p][0][kt * 16 + 2 * tg];
            unsigned a1 = *(const unsigned*)&shH[p][1][kt * 16 + 2 * tg];
            unsigned a2 = *(const unsigned*)&shH[p][0][kt * 16 + 2 * tg + 8];
            unsigned a3 = *(const unsigned*)&shH[p][1][kt * 16 + 2 * tg + 8];
            #pragma unroll
            for (int nt = 0; nt < 4; nt++) {
                asm("mma.sync.aligned.m16n8k16.row.col.f32.f16.f16.f32 "
                    "{%0,%1,%2,%3}, {%4,%5,%6,%7}, {%8,%9}, {%0,%1,%2,%3};"
                    : "+f"(d[nt][0]), "+f"(d[nt][1]), "+f"(d[nt][2]), "+f"(d[nt][3])
                    : "r"(a0), "r"(a1), "r"(a2), "r"(a3),
                      "r"(bfr[nt][kt][0]), "r"(bfr[nt][kt][1]));
            }
        }

        // ---- distributed epilogue: c0/c1 = row0, c2/c3 = row1 ----
        if (epi) {
            #pragma unroll
            for (int nt = 0; nt < 4; nt++) {
                float2 u = __half22float2(*(const __half2*)&cU[nt]);
                float p0 = rsel ? d[nt][2] : d[nt][0];
                float p1 = rsel ? d[nt][3] : d[nt][1];
                float xv = lrelu(p0 + u.x + bi[nt].x);
                float yv = lrelu(p1 + u.y + bi[nt].y);
                if (mode == 0) {
                    __half2 hh = __floats2half2_rn(xv, yv);
                    *(unsigned*)&shH[p ^ 1][rsel][coff[nt]] = *(unsigned*)&hh;
                } else {
                    *(float2*)(hx + (size_t)(step + 1) * Hh + coff[nt]) =
                        make_float2(xv, yv);
                }
            }
            #pragma unroll
            for (int nt = 0; nt < 4; nt++) cU[nt] = nU[nt];
        }

        __syncthreads();   // single barrier per step
    }
}

// ============================================================================
// Output projection (fp32 FFMA2, validated) + fused x0 row.
// ============================================================================
#define G2_ROWS 32
#define G2_SMEM (64*64*16 + G2_ROWS*Hh*4)   // 98304

__global__ void __launch_bounds__(256, 2)
gemm2_kernel(const float* __restrict__ out_h,
             const float* __restrict__ W_ho,
             const float* __restrict__ b_ho,
             const float* __restrict__ x0,
             float* __restrict__ out_x)
{
    extern __shared__ float smem[];
    float* sw = smem;            // [64 j4][64 d] float4 view
    float* sh = smem + 16384;    // [32 rows][256]

    const int t   = threadIdx.x;
    const int b   = blockIdx.y;
    const int tt0 = 1 + (int)blockIdx.x * 128;

    if (blockIdx.x == 0 && t < DOUT)
        out_x[(size_t)b * (Tt + 1) * DOUT + t] = x0[(size_t)b * DOUT + t];

    for (int i = t; i < 64 * 64; i += 256) {
        int j4 = i >> 6, d = i & 63;
        ((float4*)sw)[i] = *(const float4*)(W_ho + (size_t)d * Hh + 4 * j4);
    }

    const int d  = t & 63;
    const int rq = t >> 6;
    const float bho = __ldg(&b_ho[d]);
    const float* hsrc = out_h + (size_t)b * (Tt + 1) * Hh;
    float* xdst = out_x + (size_t)b * (Tt + 1) * DOUT;

    #pragma unroll 1
    for (int tile = 0; tile < 4; tile++) {
        const int r0 = tt0 + tile * G2_ROWS;
        __syncthreads();
        for (int i = t; i < G2_ROWS * Hh / 4; i += 256)
            ((float4*)sh)[i] = *(const float4*)(hsrc + (size_t)r0 * Hh + 4 * i);
        __syncthreads();

        unsigned long long acc[8] = {0,0,0,0,0,0,0,0};
        const float* myh = sh + rq * 8 * Hh;
        #pragma unroll 4
        for (int j4 = 0; j4 < 64; j4++) {
            ulonglong2 wv = ((const ulonglong2*)sw)[j4 * 64 + d];
            ulonglong2 hv[8];
            #pragma unroll
            for (int r = 0; r < 8; r++)
                hv[r] = *(const ulonglong2*)(myh + r * Hh + 4 * j4);
            #pragma unroll
            for (int r = 0; r < 8; r++) ffma2(acc[r], wv.x, hv[r].x);
            #pragma unroll
            for (int r = 0; r < 8; r++) ffma2(acc[r], wv.y, hv[r].y);
        }
        #pragma unroll
        for (int r = 0; r < 8; r++) {
            float2 s = unpackf2(acc[r]);
            xdst[(size_t)(r0 + rq * 8 + r) * DOUT + d] = s.x + s.y + bho;
        }
    }
}

// Keep the persistent kernel at launch index 3 mod 6 (ncu capture slot).
__global__ void nop_a_kernel() {}
__global__ void nop_b_kernel() {}
__global__ void nop_c_kernel() {}

extern "C" void kernel_launch(void* const* d_in, const int* in_sizes, int n_in,
                              void* d_out, int out_size) {
    const float* inputs = (const float*)d_in[0];
    const float* x0     = (const float*)d_in[1];
    const float* h0     = (const float*)d_in[2];
    const float* W_ih   = (const float*)d_in[3];
    const float* b_ih   = (const float*)d_in[4];
    const float* W_ho   = (const float*)d_in[5];
    const float* b_ho   = (const float*)d_in[6];

    float* out_x = (float*)d_out;                                  // [B, T+1, DOUT]
    float* out_h = out_x + (size_t)Bb * (Tt + 1) * DOUT;           // [B, T+1, H]

    cudaFuncSetAttribute(gemm2_kernel,
                         cudaFuncAttributeMaxDynamicSharedMemorySize,
                         (int)G2_SMEM);

    u_precompute_kernel<<<dim3(4, Bb * Tt / 128), 128>>>(inputs, W_ih);        // 0
    nop_a_kernel<<<1, 32>>>();                                                 // 1
    nop_b_kernel<<<1, 32>>>();                                                 // 2
    rnn_persist_kernel<<<Bb / 2, 256>>>(h0, W_ih, b_ih, out_h);                // 3
    gemm2_kernel<<<dim3(4, Bb), 256, G2_SMEM>>>(out_h, W_ho, b_ho, x0, out_x); // 4
    nop_c_kernel<<<1, 32>>>();                                                 // 5
}

// round 16
// speedup vs baseline: 1.1605x; 1.1605x over previous
#include <cuda_runtime.h>
#include <cuda_fp16.h>

// Problem constants
#define Bb    256
#define Tt    512
#define DIN   128
#define Hh    256
#define DOUT  64
#define KTOT  384
#define LEAK  0.01f

// 64MB fp16 scratch: U[b][t][h] = inputs[b][t] @ W_u^T  (k < DIN part)
__device__ __half g_U[(size_t)Bb * Tt * Hh];

__device__ __forceinline__ float lrelu(float x) {
    return x > 0.f ? x : LEAK * x;
}

#define HMMA(dd, a0, a1, a2, a3, b0, b1)                                   \
    asm("mma.sync.aligned.m16n8k16.row.col.f32.f16.f16.f32 "               \
        "{%0,%1,%2,%3}, {%4,%5,%6,%7}, {%8,%9}, {%0,%1,%2,%3};"            \
        : "+f"((dd)[0]), "+f"((dd)[1]), "+f"((dd)[2]), "+f"((dd)[3])       \
        : "r"(a0), "r"(a1), "r"(a2), "r"(a3), "r"(b0), "r"(b1))

// ============================================================================
// Persistent recurrence + integrated U prologue. 128 CTAs x 256 threads.
// Prologue: this CTA's U rows ([1024 x 256 x 128] GEMM) via the SAME validated
// fragment mapping + ki order as the old precompute -> U numerically identical.
// Loop: EXACT R12 kernel (370us, 254 regs, validated).
// ============================================================================
#define SH_PAD 264
#define PCPAD  136
#define RP_SMEM ((256 + 64) * PCPAD * 2)   // W_u[256] + A-tile[64] = 87040 B

__global__ void __launch_bounds__(256, 1)
rnn_persist_kernel(const float* __restrict__ inputs,   // [B, T, DIN]
                   const float* __restrict__ h0,       // [B, H]
                   const float* __restrict__ W_ih,     // [H, KTOT]
                   const float* __restrict__ b_ih,     // [H]
                   float* __restrict__ out_h)          // [B, T+1, H]
{
    __shared__ __half shH[2][2][SH_PAD];   // [buf][row][col]
    extern __shared__ __half psm[];
    __half* sWu = psm;                 // [256][PCPAD] fp16 W_u
    __half* sAu = psm + 256 * PCPAD;   // [64][PCPAD]  fp16 input tile

    const int t    = threadIdx.x;
    const int wi   = t >> 5;               // warp: n-cols [wi*32, wi*32+32)
    const int lane = t & 31;
    const int gg   = lane >> 2;
    const int tg   = lane & 3;
    const bool active = (lane < 8);
    const int r    = (lane >> 2) & 1;
    const int row0 = (int)blockIdx.x * 2;

    // ======================= PROLOGUE: compute my U ========================
    {
        // stage W_u = fp16(W_ih[:, 0:128])
        for (int i = t; i < 256 * 32; i += 256) {
            int row = i >> 5, c4 = i & 31;
            float4 v = *(const float4*)(W_ih + (size_t)row * KTOT + 4 * c4);
            __half2 h01 = __floats2half2_rn(v.x, v.y);
            __half2 h23 = __floats2half2_rn(v.z, v.w);
            *(uint2*)(sWu + row * PCPAD + 4 * c4) =
                make_uint2(*(unsigned*)&h01, *(unsigned*)&h23);
        }
        __syncthreads();

        // hoist this warp's B fragments (4 nf x 8 ki)
        unsigned bu[4][8][2];
        #pragma unroll
        for (int nf = 0; nf < 4; nf++)
            #pragma unroll
            for (int ki = 0; ki < 8; ki++) {
                int k0 = 16 * ki;
                bu[nf][ki][0] = *(const unsigned*)(sWu + (wi*32 + 8*nf + gg) * PCPAD + k0 + 2*tg);
                bu[nf][ki][1] = *(const unsigned*)(sWu + (wi*32 + 8*nf + gg) * PCPAD + k0 + 2*tg + 8);
            }

        #pragma unroll 1
        for (int tile = 0; tile < 16; tile++) {
            if (tile) __syncthreads();           // readers of sAu done
            for (int i = t; i < 64 * 32; i += 256) {
                int row = i >> 5, c4 = i & 31;
                int m   = tile * 64 + row;
                int rr  = m >> 9, tt = m & 511;
                float4 v = *(const float4*)(inputs + (size_t)(row0 + rr) * Tt * DIN
                                            + (size_t)tt * DIN + 4 * c4);
                __half2 h01 = __floats2half2_rn(v.x, v.y);
                __half2 h23 = __floats2half2_rn(v.z, v.w);
                *(uint2*)(sAu + row * PCPAD + 4 * c4) =
                    make_uint2(*(unsigned*)&h01, *(unsigned*)&h23);
            }
            __syncthreads();

            #pragma unroll
            for (int mf = 0; mf < 4; mf++) {
                float du[4][4];
                #pragma unroll
                for (int nf = 0; nf < 4; nf++)
                    #pragma unroll
                    for (int c = 0; c < 4; c++) du[nf][c] = 0.f;

                #pragma unroll
                for (int ki = 0; ki < 8; ki++) {
                    int k0 = 16 * ki;
                    unsigned a0 = *(const unsigned*)(sAu + (mf*16 + gg)     * PCPAD + k0 + 2*tg);
                    unsigned a1 = *(const unsigned*)(sAu + (mf*16 + 8 + gg) * PCPAD + k0 + 2*tg);
                    unsigned a2 = *(const unsigned*)(sAu + (mf*16 + gg)     * PCPAD + k0 + 2*tg + 8);
                    unsigned a3 = *(const unsigned*)(sAu + (mf*16 + 8 + gg) * PCPAD + k0 + 2*tg + 8);
                    #pragma unroll
                    for (int nf = 0; nf < 4; nf++)
                        HMMA(du[nf], a0, a1, a2, a3, bu[nf][ki][0], bu[nf][ki][1]);
                }

                #pragma unroll
                for (int nf = 0; nf < 4; nf++) {
                    __half2 lo = __floats2half2_rn(du[nf][0], du[nf][1]);
                    __half2 hi = __floats2half2_rn(du[nf][2], du[nf][3]);
                    int col = wi * 32 + nf * 8 + 2 * tg;
                    int m0g = tile * 64 + mf * 16 + gg;
                    int m1g = m0g + 8;
                    *(unsigned*)&g_U[(size_t)(row0 + (m0g >> 9)) * Tt * Hh
                                     + (size_t)(m0g & 511) * Hh + col] = *(unsigned*)&lo;
                    *(unsigned*)&g_U[(size_t)(row0 + (m1g >> 9)) * Tt * Hh
                                     + (size_t)(m1g & 511) * Hh + col] = *(unsigned*)&hi;
                }
            }
        }
        __syncthreads();   // U complete + visible (syncthreads orders gmem in-CTA)
    }

    // ======================= LOOP: exact R12 kernel ========================
    unsigned bfr[4][16][2];
    #pragma unroll
    for (int nt = 0; nt < 4; nt++) {
        const int n = wi * 32 + nt * 8 + (lane >> 2);
        const float* wr = W_ih + (size_t)n * KTOT + DIN;
        #pragma unroll
        for (int kt = 0; kt < 16; kt++) {
            float2 f0 = __ldg((const float2*)(wr + kt * 16 + 2 * tg));
            float2 f1 = __ldg((const float2*)(wr + kt * 16 + 2 * tg + 8));
            __half2 h0v = __floats2half2_rn(f0.x, f0.y);
            __half2 h1v = __floats2half2_rn(f1.x, f1.y);
            bfr[nt][kt][0] = *(unsigned*)&h0v;
            bfr[nt][kt][1] = *(unsigned*)&h1v;
        }
    }

    for (int i = t; i < 2 * Hh; i += 256) {
        int rr = i >> 8, c = i & 255;
        float v = h0[(size_t)(row0 + rr) * Hh + c];
        shH[0][rr][c] = __float2half_rn(v);
        out_h[(size_t)(row0 + rr) * (Tt + 1) * Hh + c] = v;
    }

    int coff[4];
    float2 bi[4];
    #pragma unroll
    for (int nt = 0; nt < 4; nt++) {
        coff[nt] = wi * 32 + nt * 8 + 2 * tg;
        bi[nt] = active ? __ldg((const float2*)(b_ih + coff[nt]))
                        : make_float2(0.f, 0.f);
    }
    const __half* Ub = g_U + (size_t)(row0 + r) * Tt * Hh;
    float* hx = out_h + (size_t)(row0 + r) * (Tt + 1) * Hh;

    unsigned cU[4] = {0, 0, 0, 0};
    if (active) {
        #pragma unroll
        for (int nt = 0; nt < 4; nt++)
            cU[nt] = *(const unsigned*)(Ub + coff[nt]);
    }

    const unsigned zero = 0;
    __syncthreads();

    #pragma unroll 1
    for (int step = 0; step < Tt; step++) {
        const int p = step & 1;

        unsigned nU[4] = {0, 0, 0, 0};
        if (active && step + 1 < Tt) {
            #pragma unroll
            for (int nt = 0; nt < 4; nt++)
                nU[nt] = *(const unsigned*)(Ub + (size_t)(step + 1) * Hh + coff[nt]);
        }

        float d[4][4];
        #pragma unroll
        for (int nt = 0; nt < 4; nt++)
            #pragma unroll
            for (int c = 0; c < 4; c++) d[nt][c] = 0.f;

        #pragma unroll
        for (int kt = 0; kt < 16; kt++) {
            unsigned a0 = 0, a2 = 0;
            if (active) {
                a0 = *(const unsigned*)&shH[p][r][kt * 16 + 2 * tg];
                a2 = *(const unsigned*)&shH[p][r][kt * 16 + 2 * tg + 8];
            }
            #pragma unroll
            for (int nt = 0; nt < 4; nt++)
                HMMA(d[nt], a0, zero, a2, zero, bfr[nt][kt][0], bfr[nt][kt][1]);
        }

        if (active) {
            #pragma unroll
            for (int nt = 0; nt < 4; nt++) {
                float2 u = __half22float2(*(const __half2*)&cU[nt]);
                float xv = lrelu(d[nt][0] + u.x + bi[nt].x);
                float yv = lrelu(d[nt][1] + u.y + bi[nt].y);
                __half2 hh = __floats2half2_rn(xv, yv);
                *(unsigned*)&shH[p ^ 1][r][coff[nt]] = *(unsigned*)&hh;
                *(float2*)(hx + (size_t)(step + 1) * Hh + coff[nt]) =
                    make_float2(xv, yv);
            }
        }
        #pragma unroll
        for (int nt = 0; nt < 4; nt++) cU[nt] = nU[nt];

        __syncthreads();
    }
}

// ============================================================================
// Output projection on TENSOR CORES (same validated fragment pattern).
// Grid 256 (one CTA per b), 128 threads (4 warps x 16 m-rows/tile), 8 tiles.
// K=256, N=64. h staged fp32->fp16 per tile; fp32 accum + b_ho; x0 fused.
// ============================================================================
#define G2PAD  264
#define G2_SMEM2 (128 * G2PAD * 2)   // sW[64] + sH[64] rows = 67584 B

__global__ void __launch_bounds__(128)
gemm2_kernel(const float* __restrict__ out_h,    // [B, T+1, H]
             const float* __restrict__ W_ho,     // [DOUT, H]
             const float* __restrict__ b_ho,     // [DOUT]
             const float* __restrict__ x0,       // [B, DOUT]
             float* __restrict__ out_x)          // [B, T+1, DOUT]
{
    extern __shared__ __half g2s[];
    __half* sW = g2s;               // [64][G2PAD]
    __half* sH = g2s + 64 * G2PAD;  // [64][G2PAD]

    const int t = threadIdx.x;
    const int b = blockIdx.x;

    if (t < DOUT)
        out_x[(size_t)b * (Tt + 1) * DOUT + t] = x0[(size_t)b * DOUT + t];

    // stage W_ho fp16 once
    for (int i = t; i < 64 * 64; i += 128) {
        int row = i >> 6, c4 = i & 63;
        float4 v = *(const float4*)(W_ho + (size_t)row * Hh + 4 * c4);
        __half2 h01 = __floats2half2_rn(v.x, v.y);
        __half2 h23 = __floats2half2_rn(v.z, v.w);
        *(uint2*)(sW + row * G2PAD + 4 * c4) =
            make_uint2(*(unsigned*)&h01, *(unsigned*)&h23);
    }

    const int wi = t >> 5, lane = t & 31;
    const int gg = lane >> 2, tg = lane & 3;
    const int mw = wi * 16;
    const float* hsrc = out_h + (size_t)b * (Tt + 1) * Hh;
    float* xdst = out_x + (size_t)b * (Tt + 1) * DOUT;

    #pragma unroll 1
    for (int tile = 0; tile < 8; tile++) {
        const int t0 = 1 + tile * 64;
        if (tile) __syncthreads();           // prior mma reads of sH done
        for (int i = t; i < 64 * 64; i += 128) {
            int row = i >> 6, c4 = i & 63;
            float4 v = *(const float4*)(hsrc + (size_t)(t0 + row) * Hh + 4 * c4);
            __half2 h01 = __floats2half2_rn(v.x, v.y);
            __half2 h23 = __floats2half2_rn(v.z, v.w);
            *(uint2*)(sH + row * G2PAD + 4 * c4) =
                make_uint2(*(unsigned*)&h01, *(unsigned*)&h23);
        }
        __syncthreads();

        float d[8][4];
        #pragma unroll
        for (int nf = 0; nf < 8; nf++)
            #pragma unroll
            for (int c = 0; c < 4; c++) d[nf][c] = 0.f;

        #pragma unroll
        for (int kt = 0; kt < 16; kt++) {
            int k0 = 16 * kt;
            unsigned a0 = *(const unsigned*)(sH + (mw + gg)     * G2PAD + k0 + 2*tg);
            unsigned a1 = *(const unsigned*)(sH + (mw + 8 + gg) * G2PAD + k0 + 2*tg);
            unsigned a2 = *(const unsigned*)(sH + (mw + gg)     * G2PAD + k0 + 2*tg + 8);
            unsigned a3 = *(const unsigned*)(sH + (mw + 8 + gg) * G2PAD + k0 + 2*tg + 8);
            #pragma unroll
            for (int nf = 0; nf < 8; nf++) {
                unsigned b0 = *(const unsigned*)(sW + (8*nf + gg) * G2PAD + k0 + 2*tg);
                unsigned b1 = *(const unsigned*)(sW + (8*nf + gg) * G2PAD + k0 + 2*tg + 8);
                HMMA(d[nf], a0, a1, a2, a3, b0, b1);
            }
        }

        #pragma unroll
        for (int nf = 0; nf < 8; nf++) {
            float2 bh = __ldg((const float2*)(b_ho + 8*nf + 2*tg));
            int tg0 = t0 + mw + gg, tg1 = tg0 + 8;
            *(float2*)(xdst + (size_t)tg0 * DOUT + 8*nf + 2*tg) =
                make_float2(d[nf][0] + bh.x, d[nf][1] + bh.y);
            *(float2*)(xdst + (size_t)tg1 * DOUT + 8*nf + 2*tg) =
                make_float2(d[nf][2] + bh.x, d[nf][3] + bh.y);
        }
    }
}

// Keep the persistent kernel at launch index 3 mod 6 (ncu capture slot).
__global__ void nop_a_kernel() {}
__global__ void nop_b_kernel() {}
__global__ void nop_c_kernel() {}
__global__ void nop_d_kernel() {}

extern "C" void kernel_launch(void* const* d_in, const int* in_sizes, int n_in,
                              void* d_out, int out_size) {
    const float* inputs = (const float*)d_in[0];
    const float* x0     = (const float*)d_in[1];
    const float* h0     = (const float*)d_in[2];
    const float* W_ih   = (const float*)d_in[3];
    const float* b_ih   = (const float*)d_in[4];
    const float* W_ho   = (const float*)d_in[5];
    const float* b_ho   = (const float*)d_in[6];

    float* out_x = (float*)d_out;                                  // [B, T+1, DOUT]
    float* out_h = out_x + (size_t)Bb * (Tt + 1) * DOUT;           // [B, T+1, H]

    cudaFuncSetAttribute(rnn_persist_kernel,
                         cudaFuncAttributeMaxDynamicSharedMemorySize,
                         (int)RP_SMEM);
    cudaFuncSetAttribute(gemm2_kernel,
                         cudaFuncAttributeMaxDynamicSharedMemorySize,
                         (int)G2_SMEM2);

    nop_a_kernel<<<1, 32>>>();                                                 // 0
    nop_b_kernel<<<1, 32>>>();                                                 // 1
    nop_c_kernel<<<1, 32>>>();                                                 // 2
    rnn_persist_kernel<<<Bb / 2, 256, RP_SMEM>>>(inputs, h0, W_ih,             // 3
                                                 b_ih, out_h);
    gemm2_kernel<<<Bb, 128, G2_SMEM2>>>(out_h, W_ho, b_ho, x0, out_x);         // 4
    nop_d_kernel<<<1, 32>>>();                                                 // 5
}

// round 17
// speedup vs baseline: 1.2133x; 1.0455x over previous
#include <cuda_runtime.h>
#include <cuda_fp16.h>

// Problem constants
#define Bb    256
#define Tt    512
#define DIN   128
#define Hh    256
#define DOUT  64
#define KTOT  384
#define LEAK  0.01f

// 64MB fp16 scratch: U[b][t][h] = inputs[b][t] @ W_u^T  (k < DIN part)
__device__ __half g_U[(size_t)Bb * Tt * Hh];

__device__ __forceinline__ float lrelu(float x) {
    return x > 0.f ? x : LEAK * x;
}

#define HMMA(dd, a0, a1, a2, a3, b0, b1)                                   \
    asm("mma.sync.aligned.m16n8k16.row.col.f32.f16.f16.f32 "               \
        "{%0,%1,%2,%3}, {%4,%5,%6,%7}, {%8,%9}, {%0,%1,%2,%3};"            \
        : "+f"((dd)[0]), "+f"((dd)[1]), "+f"((dd)[2]), "+f"((dd)[3])       \
        : "r"(a0), "r"(a1), "r"(a2), "r"(a3), "r"(b0), "r"(b1))

// ============================================================================
// Persistent recurrence + pipelined U prologue. 128 CTAs x 256 threads.
// Prologue v2: double-buffered input tile + register prefetch (DRAM latency
// hides under the previous tile's mma). Same fragments/ki order as R16 ->
// U bit-identical. Loop: EXACT R12 kernel (370us, validated 3x).
// ============================================================================
#define SH_PAD 264
#define PCPAD  136
// sWu[256] + sAu0[64] + sAu1[64] rows of PCPAD halves
#define RP_SMEM ((256 + 64 + 64) * PCPAD * 2)   // 104448 B

__global__ void __launch_bounds__(256, 1)
rnn_persist_kernel(const float* __restrict__ inputs,   // [B, T, DIN]
                   const float* __restrict__ h0,       // [B, H]
                   const float* __restrict__ W_ih,     // [H, KTOT]
                   const float* __restrict__ b_ih,     // [H]
                   float* __restrict__ out_h)          // [B, T+1, H]
{
    __shared__ __half shH[2][2][SH_PAD];   // [buf][row][col]
    extern __shared__ __half psm[];
    __half* sWu  = psm;                    // [256][PCPAD] fp16 W_u
    __half* sAu0 = psm + 256 * PCPAD;      // [64][PCPAD]  tile buf 0
    __half* sAu1 = sAu0 + 64 * PCPAD;      // [64][PCPAD]  tile buf 1

    const int t    = threadIdx.x;
    const int wi   = t >> 5;               // warp: n-cols [wi*32, wi*32+32)
    const int lane = t & 31;
    const int gg   = lane >> 2;
    const int tg   = lane & 3;
    const bool active = (lane < 8);
    const int r    = (lane >> 2) & 1;
    const int row0 = (int)blockIdx.x * 2;

    // ======================= PROLOGUE: compute my U ========================
    {
        // stage W_u = fp16(W_ih[:, 0:128])
        for (int i = t; i < 256 * 32; i += 256) {
            int row = i >> 5, c4 = i & 31;
            float4 v = *(const float4*)(W_ih + (size_t)row * KTOT + 4 * c4);
            __half2 h01 = __floats2half2_rn(v.x, v.y);
            __half2 h23 = __floats2half2_rn(v.z, v.w);
            *(uint2*)(sWu + row * PCPAD + 4 * c4) =
                make_uint2(*(unsigned*)&h01, *(unsigned*)&h23);
        }

        // stage tile 0 into sAu0 (each thread: 8 of the 2048 float4 slots)
        #pragma unroll
        for (int j = 0; j < 8; j++) {
            int i = t + 256 * j;                 // [0, 2048)
            int row = i >> 5, c4 = i & 31;
            int m   = row;                       // tile 0: m = row
            int rr  = m >> 9, tt = m & 511;
            float4 v = *(const float4*)(inputs + (size_t)(row0 + rr) * Tt * DIN
                                        + (size_t)tt * DIN + 4 * c4);
            __half2 h01 = __floats2half2_rn(v.x, v.y);
            __half2 h23 = __floats2half2_rn(v.z, v.w);
            *(uint2*)(sAu0 + row * PCPAD + 4 * c4) =
                make_uint2(*(unsigned*)&h01, *(unsigned*)&h23);
        }
        __syncthreads();

        // hoist this warp's B fragments (4 nf x 8 ki)
        unsigned bu[4][8][2];
        #pragma unroll
        for (int nf = 0; nf < 4; nf++)
            #pragma unroll
            for (int ki = 0; ki < 8; ki++) {
                int k0 = 16 * ki;
                bu[nf][ki][0] = *(const unsigned*)(sWu + (wi*32 + 8*nf + gg) * PCPAD + k0 + 2*tg);
                bu[nf][ki][1] = *(const unsigned*)(sWu + (wi*32 + 8*nf + gg) * PCPAD + k0 + 2*tg + 8);
            }

        #pragma unroll 1
        for (int tile = 0; tile < 16; tile++) {
            const __half* cur = (tile & 1) ? sAu1 : sAu0;
            __half*       nxt = (tile & 1) ? sAu0 : sAu1;

            // issue next tile's DRAM loads NOW (latency hides under mma)
            float4 pv[8];
            if (tile + 1 < 16) {
                #pragma unroll
                for (int j = 0; j < 8; j++) {
                    int i = t + 256 * j;
                    int row = i >> 5, c4 = i & 31;
                    int m   = (tile + 1) * 64 + row;
                    int rr  = m >> 9, tt = m & 511;
                    pv[j] = *(const float4*)(inputs + (size_t)(row0 + rr) * Tt * DIN
                                             + (size_t)tt * DIN + 4 * c4);
                }
            }

            // mma on current tile (identical math/order to R16)
            #pragma unroll
            for (int mf = 0; mf < 4; mf++) {
                float du[4][4];
                #pragma unroll
                for (int nf = 0; nf < 4; nf++)
                    #pragma unroll
                    for (int c = 0; c < 4; c++) du[nf][c] = 0.f;

                #pragma unroll
                for (int ki = 0; ki < 8; ki++) {
                    int k0 = 16 * ki;
                    unsigned a0 = *(const unsigned*)(cur + (mf*16 + gg)     * PCPAD + k0 + 2*tg);
                    unsigned a1 = *(const unsigned*)(cur + (mf*16 + 8 + gg) * PCPAD + k0 + 2*tg);
                    unsigned a2 = *(const unsigned*)(cur + (mf*16 + gg)     * PCPAD + k0 + 2*tg + 8);
                    unsigned a3 = *(const unsigned*)(cur + (mf*16 + 8 + gg) * PCPAD + k0 + 2*tg + 8);
                    #pragma unroll
                    for (int nf = 0; nf < 4; nf++)
                        HMMA(du[nf], a0, a1, a2, a3, bu[nf][ki][0], bu[nf][ki][1]);
                }

                #pragma unroll
                for (int nf = 0; nf < 4; nf++) {
                    __half2 lo = __floats2half2_rn(du[nf][0], du[nf][1]);
                    __half2 hi = __floats2half2_rn(du[nf][2], du[nf][3]);
                    int col = wi * 32 + nf * 8 + 2 * tg;
                    int m0g = tile * 64 + mf * 16 + gg;
                    int m1g = m0g + 8;
                    *(unsigned*)&g_U[(size_t)(row0 + (m0g >> 9)) * Tt * Hh
                                     + (size_t)(m0g & 511) * Hh + col] = *(unsigned*)&lo;
                    *(unsigned*)&g_U[(size_t)(row0 + (m1g >> 9)) * Tt * Hh
                                     + (size_t)(m1g & 511) * Hh + col] = *(unsigned*)&hi;
                }
            }

            // install prefetched tile into the other buffer
            if (tile + 1 < 16) {
                #pragma unroll
                for (int j = 0; j < 8; j++) {
                    int i = t + 256 * j;
                    int row = i >> 5, c4 = i & 31;
                    __half2 h01 = __floats2half2_rn(pv[j].x, pv[j].y);
                    __half2 h23 = __floats2half2_rn(pv[j].z, pv[j].w);
                    *(uint2*)(nxt + row * PCPAD + 4 * c4) =
                        make_uint2(*(unsigned*)&h01, *(unsigned*)&h23);
                }
            }
            __syncthreads();   // single barrier per tile
        }
        __syncthreads();   // U complete + visible
    }

    // ======================= LOOP: exact R12 kernel ========================
    unsigned bfr[4][16][2];
    #pragma unroll
    for (int nt = 0; nt < 4; nt++) {
        const int n = wi * 32 + nt * 8 + (lane >> 2);
        const float* wr = W_ih + (size_t)n * KTOT + DIN;
        #pragma unroll
        for (int kt = 0; kt < 16; kt++) {
            float2 f0 = __ldg((const float2*)(wr + kt * 16 + 2 * tg));
            float2 f1 = __ldg((const float2*)(wr + kt * 16 + 2 * tg + 8));
            __half2 h0v = __floats2half2_rn(f0.x, f0.y);
            __half2 h1v = __floats2half2_rn(f1.x, f1.y);
            bfr[nt][kt][0] = *(unsigned*)&h0v;
            bfr[nt][kt][1] = *(unsigned*)&h1v;
        }
    }

    for (int i = t; i < 2 * Hh; i += 256) {
        int rr = i >> 8, c = i & 255;
        float v = h0[(size_t)(row0 + rr) * Hh + c];
        shH[0][rr][c] = __float2half_rn(v);
        out_h[(size_t)(row0 + rr) * (Tt + 1) * Hh + c] = v;
    }

    int coff[4];
    float2 bi[4];
    #pragma unroll
    for (int nt = 0; nt < 4; nt++) {
        coff[nt] = wi * 32 + nt * 8 + 2 * tg;
        bi[nt] = active ? __ldg((const float2*)(b_ih + coff[nt]))
                        : make_float2(0.f, 0.f);
    }
    const __half* Ub = g_U + (size_t)(row0 + r) * Tt * Hh;
    float* hx = out_h + (size_t)(row0 + r) * (Tt + 1) * Hh;

    unsigned cU[4] = {0, 0, 0, 0};
    if (active) {
        #pragma unroll
        for (int nt = 0; nt < 4; nt++)
            cU[nt] = *(const unsigned*)(Ub + coff[nt]);
    }

    const unsigned zero = 0;
    __syncthreads();

    #pragma unroll 1
    for (int step = 0; step < Tt; step++) {
        const int p = step & 1;

        unsigned nU[4] = {0, 0, 0, 0};
        if (active && step + 1 < Tt) {
            #pragma unroll
            for (int nt = 0; nt < 4; nt++)
                nU[nt] = *(const unsigned*)(Ub + (size_t)(step + 1) * Hh + coff[nt]);
        }

        float d[4][4];
        #pragma unroll
        for (int nt = 0; nt < 4; nt++)
            #pragma unroll
            for (int c = 0; c < 4; c++) d[nt][c] = 0.f;

        #pragma unroll
        for (int kt = 0; kt < 16; kt++) {
            unsigned a0 = 0, a2 = 0;
            if (active) {
                a0 = *(const unsigned*)&shH[p][r][kt * 16 + 2 * tg];
                a2 = *(const unsigned*)&shH[p][r][kt * 16 + 2 * tg + 8];
            }
            #pragma unroll
            for (int nt = 0; nt < 4; nt++)
                HMMA(d[nt], a0, zero, a2, zero, bfr[nt][kt][0], bfr[nt][kt][1]);
        }

        if (active) {
            #pragma unroll
            for (int nt = 0; nt < 4; nt++) {
                float2 u = __half22float2(*(const __half2*)&cU[nt]);
                float xv = lrelu(d[nt][0] + u.x + bi[nt].x);
                float yv = lrelu(d[nt][1] + u.y + bi[nt].y);
                __half2 hh = __floats2half2_rn(xv, yv);
                *(unsigned*)&shH[p ^ 1][r][coff[nt]] = *(unsigned*)&hh;
                *(float2*)(hx + (size_t)(step + 1) * Hh + coff[nt]) =
                    make_float2(xv, yv);
            }
        }
        #pragma unroll
        for (int nt = 0; nt < 4; nt++) cU[nt] = nU[nt];

        __syncthreads();
    }
}

// ============================================================================
// Output projection on TENSOR CORES (validated R16 kernel).
// SPLIT: grid (2, 256) — each CTA does 4 of the 8 t-tiles for its b.
// smem 67.5 KB -> 3 CTAs/SM co-residency, better latency hiding.
// ============================================================================
#define G2PAD  264
#define G2_SMEM2 (128 * G2PAD * 2)   // sW[64] + sH[64] rows = 67584 B

__global__ void __launch_bounds__(128)
gemm2_kernel(const float* __restrict__ out_h,    // [B, T+1, H]
             const float* __restrict__ W_ho,     // [DOUT, H]
             const float* __restrict__ b_ho,     // [DOUT]
             const float* __restrict__ x0,       // [B, DOUT]
             float* __restrict__ out_x)          // [B, T+1, DOUT]
{
    extern __shared__ __half g2s[];
    __half* sW = g2s;               // [64][G2PAD]
    __half* sH = g2s + 64 * G2PAD;  // [64][G2PAD]

    const int t = threadIdx.x;
    const int b = blockIdx.y;
    const int half = blockIdx.x;    // 0: tiles 0-3, 1: tiles 4-7

    if (half == 0 && t < DOUT)
        out_x[(size_t)b * (Tt + 1) * DOUT + t] = x0[(size_t)b * DOUT + t];

    // stage W_ho fp16 once
    for (int i = t; i < 64 * 64; i += 128) {
        int row = i >> 6, c4 = i & 63;
        float4 v = *(const float4*)(W_ho + (size_t)row * Hh + 4 * c4);
        __half2 h01 = __floats2half2_rn(v.x, v.y);
        __half2 h23 = __floats2half2_rn(v.z, v.w);
        *(uint2*)(sW + row * G2PAD + 4 * c4) =
            make_uint2(*(unsigned*)&h01, *(unsigned*)&h23);
    }

    const int wi = t >> 5, lane = t & 31;
    const int gg = lane >> 2, tg = lane & 3;
    const int mw = wi * 16;
    const float* hsrc = out_h + (size_t)b * (Tt + 1) * Hh;
    float* xdst = out_x + (size_t)b * (Tt + 1) * DOUT;

    #pragma unroll 1
    for (int tl = 0; tl < 4; tl++) {
        const int tile = half * 4 + tl;
        const int t0 = 1 + tile * 64;
        if (tl) __syncthreads();           // prior mma reads of sH done
        for (int i = t; i < 64 * 64; i += 128) {
            int row = i >> 6, c4 = i & 63;
            float4 v = *(const float4*)(hsrc + (size_t)(t0 + row) * Hh + 4 * c4);
            __half2 h01 = __floats2half2_rn(v.x, v.y);
            __half2 h23 = __floats2half2_rn(v.z, v.w);
            *(uint2*)(sH + row * G2PAD + 4 * c4) =
                make_uint2(*(unsigned*)&h01, *(unsigned*)&h23);
        }
        __syncthreads();

        float d[8][4];
        #pragma unroll
        for (int nf = 0; nf < 8; nf++)
            #pragma unroll
            for (int c = 0; c < 4; c++) d[nf][c] = 0.f;

        #pragma unroll
        for (int kt = 0; kt < 16; kt++) {
            int k0 = 16 * kt;
            unsigned a0 = *(const unsigned*)(sH + (mw + gg)     * G2PAD + k0 + 2*tg);
            unsigned a1 = *(const unsigned*)(sH + (mw + 8 + gg) * G2PAD + k0 + 2*tg);
            unsigned a2 = *(const unsigned*)(sH + (mw + gg)     * G2PAD + k0 + 2*tg + 8);
            unsigned a3 = *(const unsigned*)(sH + (mw + 8 + gg) * G2PAD + k0 + 2*tg + 8);
            #pragma unroll
            for (int nf = 0; nf < 8; nf++) {
                unsigned b0 = *(const unsigned*)(sW + (8*nf + gg) * G2PAD + k0 + 2*tg);
                unsigned b1 = *(const unsigned*)(sW + (8*nf + gg) * G2PAD + k0 + 2*tg + 8);
                HMMA(d[nf], a0, a1, a2, a3, b0, b1);
            }
        }

        #pragma unroll
        for (int nf = 0; nf < 8; nf++) {
            float2 bh = __ldg((const float2*)(b_ho + 8*nf + 2*tg));
            int tg0 = t0 + mw + gg, tg1 = tg0 + 8;
            *(float2*)(xdst + (size_t)tg0 * DOUT + 8*nf + 2*tg) =
                make_float2(d[nf][0] + bh.x, d[nf][1] + bh.y);
            *(float2*)(xdst + (size_t)tg1 * DOUT + 8*nf + 2*tg) =
                make_float2(d[nf][2] + bh.x, d[nf][3] + bh.y);
        }
    }
}

// Keep the persistent kernel at launch index 3 mod 6 (ncu capture slot).
__global__ void nop_a_kernel() {}
__global__ void nop_b_kernel() {}
__global__ void nop_c_kernel() {}
__global__ void nop_d_kernel() {}

extern "C" void kernel_launch(void* const* d_in, const int* in_sizes, int n_in,
                              void* d_out, int out_size) {
    const float* inputs = (const float*)d_in[0];
    const float* x0     = (const float*)d_in[1];
    const float* h0     = (const float*)d_in[2];
    const float* W_ih   = (const float*)d_in[3];
    const float* b_ih   = (const float*)d_in[4];
    const float* W_ho   = (const float*)d_in[5];
    const float* b_ho   = (const float*)d_in[6];

    float* out_x = (float*)d_out;                                  // [B, T+1, DOUT]
    float* out_h = out_x + (size_t)Bb * (Tt + 1) * DOUT;           // [B, T+1, H]

    cudaFuncSetAttribute(rnn_persist_kernel,
                         cudaFuncAttributeMaxDynamicSharedMemorySize,
                         (int)RP_SMEM);
    cudaFuncSetAttribute(gemm2_kernel,
                         cudaFuncAttributeMaxDynamicSharedMemorySize,
                         (int)G2_SMEM2);

    nop_a_kernel<<<1, 32>>>();                                                 // 0
    nop_b_kernel<<<1, 32>>>();                                                 // 1
    nop_c_kernel<<<1, 32>>>();                                                 // 2
    rnn_persist_kernel<<<Bb / 2, 256, RP_SMEM>>>(inputs, h0, W_ih,             // 3
                                                 b_ih, out_h);
    gemm2_kernel<<<dim3(2, Bb), 128, G2_SMEM2>>>(out_h, W_ho, b_ho, x0, out_x);// 4
    nop_d_kernel<<<1, 32>>>();                                                 // 5
}